// round 1
// baseline (speedup 1.0000x reference)
#include <cuda_runtime.h>

#define NR 512
#define NZ 512

__global__ void __launch_bounds__(256) interp_kernel(
    const float* __restrict__ r,
    const float* __restrict__ z,
    const float* __restrict__ tt,
    float* __restrict__ out,
    int n4)
{
    int i = blockIdx.x * blockDim.x + threadIdx.x;
    if (i >= n4) return;

    float4 rv = reinterpret_cast<const float4*>(r)[i];
    float4 zv = reinterpret_cast<const float4*>(z)[i];
    float4 o;

    float rr[4] = {rv.x, rv.y, rv.z, rv.w};
    float zz[4] = {zv.x, zv.y, zv.z, zv.w};
    float res[4];

#pragma unroll
    for (int k = 0; k < 4; k++) {
        // h=1, grid0=0 -> cell index is clamped floor
        float frf = floorf(rr[k]);
        float fzf = floorf(zz[k]);
        frf = fminf(fmaxf(frf, 0.0f), (float)(NR - 2));
        fzf = fminf(fmaxf(fzf, 0.0f), (float)(NZ - 2));
        int ir0 = (int)frf;
        int iz0 = (int)fzf;

        // weights (inv = 1 since h=1)
        float wr1 = rr[k] - frf;        // r - x1
        float wr0 = (frf + 1.0f) - rr[k]; // x2 - r
        float wz1 = zz[k] - fzf;
        float wz0 = (fzf + 1.0f) - zz[k];

        int idx = ir0 * NZ + iz0;
        float Q11 = __ldg(tt + idx);
        float Q12 = __ldg(tt + idx + 1);
        float Q21 = __ldg(tt + idx + NZ);
        float Q22 = __ldg(tt + idx + NZ + 1);

        res[k] = Q11 * (wr0 * wz0)
               + Q21 * (wr1 * wz0)
               + Q12 * (wr0 * wz1)
               + Q22 * (wr1 * wz1);
    }

    o.x = res[0]; o.y = res[1]; o.z = res[2]; o.w = res[3];
    reinterpret_cast<float4*>(out)[i] = o;
}

extern "C" void kernel_launch(void* const* d_in, const int* in_sizes, int n_in,
                              void* d_out, int out_size) {
    const float* r  = (const float*)d_in[0];
    const float* z  = (const float*)d_in[1];
    const float* tt = (const float*)d_in[2];
    float* out = (float*)d_out;

    int n = in_sizes[0];          // 20,000,000 (divisible by 4)
    int n4 = n / 4;               // 5,000,000
    int threads = 256;
    int blocks = (n4 + threads - 1) / threads;
    interp_kernel<<<blocks, threads>>>(r, z, tt, out, n4);
}

// round 2
// speedup vs baseline: 4.1222x; 4.1222x over previous
#include <cuda_runtime.h>

#define NR 512
#define NZ 512

// Quad table: qt[ir*512+iz] = (tt[ir][iz], tt[ir][iz+1], tt[ir+1][iz], tt[ir+1][iz+1])
// Valid for ir,iz in [0,510]. 512*512*16B = 4MB, fits L2.
__device__ float4 g_qt[NR * NZ];

__global__ void __launch_bounds__(256) build_qt_kernel(const float* __restrict__ tt) {
    int t = blockIdx.x * blockDim.x + threadIdx.x;
    if (t >= NR * NZ) return;
    int ir = t >> 9;
    int iz = t & 511;
    if (ir >= NR - 1 || iz >= NZ - 1) return;
    float4 q;
    q.x = tt[t];            // Q11
    q.y = tt[t + 1];        // Q12
    q.z = tt[t + NZ];       // Q21
    q.w = tt[t + NZ + 1];   // Q22
    g_qt[t] = q;
}

__global__ void __launch_bounds__(256) interp_kernel(
    const float* __restrict__ r,
    const float* __restrict__ z,
    float* __restrict__ out,
    int n4)
{
    int i = blockIdx.x * blockDim.x + threadIdx.x;
    if (i >= n4) return;

    float4 rv = reinterpret_cast<const float4*>(r)[i];
    float4 zv = reinterpret_cast<const float4*>(z)[i];

    float rr[4] = {rv.x, rv.y, rv.z, rv.w};
    float zz[4] = {zv.x, zv.y, zv.z, zv.w};
    float res[4];

#pragma unroll
    for (int k = 0; k < 4; k++) {
        float frf = floorf(rr[k]);
        float fzf = floorf(zz[k]);
        frf = fminf(fmaxf(frf, 0.0f), (float)(NR - 2));
        fzf = fminf(fmaxf(fzf, 0.0f), (float)(NZ - 2));
        int ir0 = (int)frf;
        int iz0 = (int)fzf;

        float wr1 = rr[k] - frf;          // r - x1
        float wr0 = (frf + 1.0f) - rr[k]; // x2 - r
        float wz1 = zz[k] - fzf;
        float wz0 = (fzf + 1.0f) - zz[k];

        float4 q = __ldg(&g_qt[(ir0 << 9) + iz0]);

        res[k] = q.x * (wr0 * wz0)
               + q.z * (wr1 * wz0)
               + q.y * (wr0 * wz1)
               + q.w * (wr1 * wz1);
    }

    float4 o;
    o.x = res[0]; o.y = res[1]; o.z = res[2]; o.w = res[3];
    reinterpret_cast<float4*>(out)[i] = o;
}

extern "C" void kernel_launch(void* const* d_in, const int* in_sizes, int n_in,
                              void* d_out, int out_size) {
    const float* r  = (const float*)d_in[0];
    const float* z  = (const float*)d_in[1];
    const float* tt = (const float*)d_in[2];
    float* out = (float*)d_out;

    int n = in_sizes[0];          // 20,000,000
    int n4 = n / 4;               // 5,000,000

    build_qt_kernel<<<(NR * NZ + 255) / 256, 256>>>(tt);

    int threads = 256;
    int blocks = (n4 + threads - 1) / threads;
    interp_kernel<<<blocks, threads>>>(r, z, out, n4);
}